// round 17
// baseline (speedup 1.0000x reference)
#include <cuda_runtime.h>
#include <cuda_fp16.h>
#include <cstdint>

#define NNODES 100000
#define NEDGES 1600000
#define NGRAPH 512
#define RDIM   6656

#define W_C1W1 0
#define W_C1W2 8192
#define W_C2W1 24576
#define W_C2W2 40960
#define W_C3W1 57344
#define W_C3W2 90112
#define W_O1W  155648
#define W_O3W  22306816
#define W_TOTAL 22732800

#define NSCANB ((NNODES + 1023) / 1024)

// ---- static device scratch (no allocations allowed) ----
static __device__ __align__(16) __half g_xh   [NNODES * 64];
static __device__ __align__(16) __half g_aggrh[NNODES * 256];
static __device__ __align__(16) __half g_tmph [NNODES * 256];
static __device__ __align__(16) __half g_hh   [NNODES * 256];
static __device__ __align__(16) __half g_wh   [W_TOTAL];
static __device__ __align__(16) __half g_poolh[NGRAPH * RDIM];
static __device__ __align__(16) float  g_scr  [10 * 1024 * 1024];
static __device__ int g_deg[NNODES];
static __device__ int g_cursor[NNODES];
static __device__ int g_rowptr[NNODES + 1];
static __device__ int g_srclist[NEDGES];
static __device__ int g_gstart[NGRAPH + 1];
static __device__ int g_bsum[NSCANB + 1];

// ---------------------------------------------------------------------------
// CSR build
// ---------------------------------------------------------------------------
__global__ void hist_kernel(const int* __restrict__ edst, int* __restrict__ deg) {
    int base = (blockIdx.x * blockDim.x + threadIdx.x) * 4;
    #pragma unroll
    for (int q = 0; q < 4; q++) {
        int e = base + q;
        if (e < NEDGES) atomicAdd(&deg[__ldg(edst + e)], 1);
    }
}
__global__ __launch_bounds__(1024) void bsum_kernel(const int* __restrict__ deg, int* __restrict__ bsum) {
    __shared__ int red[1024];
    int t = threadIdx.x;
    int idx = blockIdx.x * 1024 + t;
    red[t] = (idx < NNODES) ? deg[idx] : 0;
    __syncthreads();
    for (int off = 512; off > 0; off >>= 1) {
        if (t < off) red[t] += red[t + off];
        __syncthreads();
    }
    if (t == 0) bsum[blockIdx.x] = red[0];
}
__global__ void boff_kernel(int* __restrict__ bsum, int* __restrict__ rowptr) {
    int run = 0;
    for (int b = 0; b < NSCANB; b++) { int v = bsum[b]; bsum[b] = run; run += v; }
    rowptr[NNODES] = run;
}
__global__ __launch_bounds__(1024) void rowptr_kernel(const int* __restrict__ deg,
                                                      const int* __restrict__ bsum,
                                                      int* __restrict__ rowptr,
                                                      int* __restrict__ cursor) {
    __shared__ int s[1024];
    int t = threadIdx.x;
    int idx = blockIdx.x * 1024 + t;
    int v = (idx < NNODES) ? deg[idx] : 0;
    s[t] = v;
    __syncthreads();
    for (int off = 1; off < 1024; off <<= 1) {
        int u = (t >= off) ? s[t - off] : 0;
        __syncthreads();
        s[t] += u;
        __syncthreads();
    }
    if (idx < NNODES) {
        int ex = s[t] - v + __ldg(bsum + blockIdx.x);
        rowptr[idx] = ex;
        cursor[idx] = ex;
    }
}
__global__ void fill_kernel(const int* __restrict__ esrc, const int* __restrict__ edst,
                            int* __restrict__ cursor, int* __restrict__ srclist) {
    int base = (blockIdx.x * blockDim.x + threadIdx.x) * 4;
    #pragma unroll
    for (int q = 0; q < 4; q++) {
        int e = base + q;
        if (e < NEDGES) {
            int d = __ldg(edst + e);
            int pos = atomicAdd(&cursor[d], 1);
            srclist[pos] = __ldg(esrc + e);
        }
    }
}
__global__ void gstart_kernel(const int* __restrict__ batch, int* __restrict__ gstart) {
    int g = blockIdx.x * blockDim.x + threadIdx.x;
    if (g > NGRAPH) return;
    if (g == NGRAPH) { gstart[NGRAPH] = NNODES; return; }
    int lo = 0, hi = NNODES;
    while (lo < hi) {
        int mid = (lo + hi) >> 1;
        if (__ldg(batch + mid) < g) lo = mid + 1; else hi = mid;
    }
    gstart[g] = lo;
}

// ---------------------------------------------------------------------------
// converts
// ---------------------------------------------------------------------------
__global__ void f2h_kernel(const float2* __restrict__ in, __half2* __restrict__ out, int n2) {
    int i = blockIdx.x * blockDim.x + threadIdx.x;
    if (i < n2) {
        float2 v = __ldg(in + i);
        out[i] = __floats2half2_rn(v.x, v.y);
    }
}
struct WSeg { const float2* src; __half2* dst; int n; };
struct WConvArgs { WSeg seg[8]; int total; };
__global__ void wconv_kernel(WConvArgs a) {
    int stride = gridDim.x * blockDim.x;
    for (int idx = blockIdx.x * blockDim.x + threadIdx.x; idx < a.total; idx += stride) {
        int i = idx;
        #pragma unroll
        for (int s = 0; s < 8; s++) {
            if (i < a.seg[s].n) {
                float2 v = __ldg(a.seg[s].src + i);
                a.seg[s].dst[i] = __floats2half2_rn(v.x, v.y);
                break;
            }
            i -= a.seg[s].n;
        }
    }
}

// ---------------------------------------------------------------------------
// standalone gather (conv3 only)
// ---------------------------------------------------------------------------
__device__ __forceinline__ float2 h2f2(uint32_t h) {
    return __half22float2(*(__half2*)&h);
}
__device__ __forceinline__ void acc4(float2* a, const uint4& t) {
    float2 v0 = h2f2(t.x), v1 = h2f2(t.y), v2 = h2f2(t.z), v3 = h2f2(t.w);
    a[0].x += v0.x; a[0].y += v0.y;
    a[1].x += v1.x; a[1].y += v1.y;
    a[2].x += v2.x; a[2].y += v2.y;
    a[3].x += v3.x; a[3].y += v3.y;
}
template<int FH>
__global__ void gather_aggr_h_kernel(const uint4* __restrict__ feat,
                                     const int* __restrict__ rowptr,
                                     const int* __restrict__ srclist,
                                     uint4* __restrict__ aggr) {
    constexpr int L = FH / 8;
    constexpr int NPB = 256 / L;
    int i = blockIdx.x * NPB + threadIdx.x / L;
    if (i >= NNODES) return;
    int c = threadIdx.x % L;

    float2 a[4];
    {
        uint4 v0 = __ldg(&feat[i * L + c]);
        a[0] = h2f2(v0.x); a[1] = h2f2(v0.y); a[2] = h2f2(v0.z); a[3] = h2f2(v0.w);
    }
    int j = __ldg(rowptr + i);
    const int end = __ldg(rowptr + i + 1);
    for (; j + 3 < end; j += 4) {
        int s0 = __ldg(srclist + j);
        int s1 = __ldg(srclist + j + 1);
        int s2 = __ldg(srclist + j + 2);
        int s3 = __ldg(srclist + j + 3);
        uint4 t0 = __ldg(&feat[s0 * L + c]);
        uint4 t1 = __ldg(&feat[s1 * L + c]);
        uint4 t2 = __ldg(&feat[s2 * L + c]);
        uint4 t3 = __ldg(&feat[s3 * L + c]);
        acc4(a, t0); acc4(a, t1); acc4(a, t2); acc4(a, t3);
    }
    for (; j < end; j++) {
        int s0 = __ldg(srclist + j);
        uint4 t0 = __ldg(&feat[s0 * L + c]);
        acc4(a, t0);
    }
    __half2 r0 = __floats2half2_rn(a[0].x, a[0].y);
    __half2 r1 = __floats2half2_rn(a[1].x, a[1].y);
    __half2 r2 = __floats2half2_rn(a[2].x, a[2].y);
    __half2 r3 = __floats2half2_rn(a[3].x, a[3].y);
    uint4 o;
    o.x = *(uint32_t*)&r0; o.y = *(uint32_t*)&r1;
    o.z = *(uint32_t*)&r2; o.w = *(uint32_t*)&r3;
    aggr[i * L + c] = o;
}

// ---------------------------------------------------------------------------
// pools / copies / reductions
// ---------------------------------------------------------------------------
__global__ void seg_pool_h_kernel(const __half2* __restrict__ feat,
                                  const int* __restrict__ gstart,
                                  __half2* __restrict__ pool,
                                  int F2, int off2) {
    int g = blockIdx.x;
    int t = threadIdx.x;
    int beg = __ldg(gstart + g), end = __ldg(gstart + g + 1);
    float2 a0 = make_float2(0.f, 0.f), a1 = make_float2(0.f, 0.f);
    int r = beg;
    for (; r + 1 < end; r += 2) {
        float2 v0 = __half22float2(__ldg(feat + (long long)r * F2 + t));
        float2 v1 = __half22float2(__ldg(feat + (long long)(r + 1) * F2 + t));
        a0.x += v0.x; a0.y += v0.y; a1.x += v1.x; a1.y += v1.y;
    }
    if (r < end) {
        float2 v0 = __half22float2(__ldg(feat + (long long)r * F2 + t));
        a0.x += v0.x; a0.y += v0.y;
    }
    pool[(long long)g * (RDIM / 2) + off2 + t] = __floats2half2_rn(a0.x + a1.x, a0.y + a1.y);
}
__global__ void fp_copy_kernel(const float4* __restrict__ fp, uint2* __restrict__ pool) {
    int col = blockIdx.x * blockDim.x + threadIdx.x;
    int row = blockIdx.y;
    if (col >= 1536) return;
    float4 v = __ldg(fp + row * 1536 + col);
    __half2 h0 = __floats2half2_rn(v.x, v.y);
    __half2 h1 = __floats2half2_rn(v.z, v.w);
    uint2 o;
    o.x = *(uint32_t*)&h0; o.y = *(uint32_t*)&h1;
    pool[row * (RDIM / 4) + 128 + col] = o;
}
__global__ void final_reduce_kernel(const float* __restrict__ part,
                                    const float* __restrict__ bias,
                                    float* __restrict__ out) {
    int idx = blockIdx.x * blockDim.x + threadIdx.x;
    if (idx >= NGRAPH * 128) return;
    float s = 0.0f;
    #pragma unroll
    for (int z = 0; z < 8; z++) s += part[idx + z * NGRAPH * 128];
    out[idx] = s + __ldg(bias + (idx & 127));
}

// ---------------------------------------------------------------------------
// shared GEMM machinery
// ---------------------------------------------------------------------------
#define SKA2 40
#define SKB2 136
#define A_STG (128 * SKA2)
#define B_STG (32 * SKB2)
#define HG_SMEM (3 * (A_STG + B_STG) * 2)
#define AT_STG (128 * SKB2)
#define GF_SMEM ((2 * AT_STG + 3 * B_STG) * 2)

__device__ __forceinline__ uint32_t smem_u32(const void* p) {
    uint32_t a;
    asm("{ .reg .u64 t; cvta.to.shared.u64 t, %1; cvt.u32.u64 %0, t; }" : "=r"(a) : "l"(p));
    return a;
}
__device__ __forceinline__ void cp16(uint32_t s, const void* g, int sz) {
    asm volatile("cp.async.cg.shared.global [%0], [%1], 16, %2;" :: "r"(s), "l"(g), "r"(sz));
}
#define CP_COMMIT() asm volatile("cp.async.commit_group;")
#define LDMATRIX_X4(r0, r1, r2, r3, addr) \
    asm volatile("ldmatrix.sync.aligned.m8n8.x4.shared.b16 {%0,%1,%2,%3}, [%4];" \
        : "=r"(r0), "=r"(r1), "=r"(r2), "=r"(r3) : "r"(addr))
#define LDMATRIX_X4_T(r0, r1, r2, r3, addr) \
    asm volatile("ldmatrix.sync.aligned.m8n8.x4.trans.shared.b16 {%0,%1,%2,%3}, [%4];" \
        : "=r"(r0), "=r"(r1), "=r"(r2), "=r"(r3) : "r"(addr))
#define HMMA16816(acc, a0, a1, a2, a3, b0, b1) \
    asm volatile("mma.sync.aligned.m16n8k16.row.col.f32.f16.f16.f32 " \
        "{%0,%1,%2,%3}, {%4,%5,%6,%7}, {%8,%9}, {%0,%1,%2,%3};" \
        : "+f"((acc)[0]), "+f"((acc)[1]), "+f"((acc)[2]), "+f"((acc)[3]) \
        : "r"(a0), "r"(a1), "r"(a2), "r"(a3), "r"(b0), "r"(b1))

// ---------------------------------------------------------------------------
// unfused GEMM (conv3 + readout). EPI 3 fuses the 4-slot split-K reduce.
// ---------------------------------------------------------------------------
template<int EPI, int SPLIT, bool CH>
__global__ __launch_bounds__(256, 2) void hgemm16_kernel(
    int M, int Nn, int K, int ldA, int zoff,
    const __half* __restrict__ A, const __half* __restrict__ B,
    const float* __restrict__ bias,
    const float* __restrict__ bng, const float* __restrict__ bnb,
    const float* __restrict__ red,
    void* __restrict__ Cv)
{
    extern __shared__ __half dsm[];
    __half* AsBase = dsm;
    __half* BsBase = dsm + 3 * A_STG;

    const int tid = threadIdx.x, bx = blockIdx.x, by = blockIdx.y, bz = blockIdx.z;
    const int warp = tid >> 5, lane = tid & 31;
    const int wm = (warp >> 2) * 64;
    const int wn = (warp & 3) * 32;
    const int lr = lane >> 2;
    const int lc = lane & 3;

    const long long koff = (long long)bz * K;

    auto issueT = [&](int kk, int stg) {
        __half* As = AsBase + stg * A_STG;
        __half* Bs = BsBase + stg * B_STG;
        #pragma unroll
        for (int q = 0; q < 2; q++) {
            int c = tid + q * 256;
            int row = c >> 2, kc = (c & 3) * 8;
            int gr = by * 128 + row;
            uint32_t sa = smem_u32(&As[row * SKA2 + kc]);
            const __half* g = A + (long long)gr * ldA + koff + kk + kc;
            cp16(sa, g, gr < M ? 16 : 0);
        }
        #pragma unroll
        for (int q = 0; q < 2; q++) {
            int c = tid + q * 256;
            int row = c >> 4, nc = (c & 15) * 8;
            uint32_t sb = smem_u32(&Bs[row * SKB2 + nc]);
            const __half* g = B + (koff + kk + row) * (long long)Nn + (long long)bx * 128 + nc;
            cp16(sb, g, 16);
        }
        CP_COMMIT();
    };

    float acc[4][4][4];
    #pragma unroll
    for (int i = 0; i < 4; i++)
        #pragma unroll
        for (int j = 0; j < 4; j++)
            #pragma unroll
            for (int t = 0; t < 4; t++) acc[i][j][t] = 0.0f;

    const int a_r = lane & 15, a_s = lane >> 4;
    const int b_k = lane & 7,  b_s = lane >> 3;

    auto compute = [&](int stg) {
        const uint32_t aB = smem_u32(AsBase + stg * A_STG);
        const uint32_t bB = smem_u32(BsBase + stg * B_STG);
        #pragma unroll
        for (int ks = 0; ks < 32; ks += 16) {
            uint32_t af[4][4], bf[4][2];
            #pragma unroll
            for (int mt = 0; mt < 4; mt++) {
                uint32_t addr = aB + (uint32_t)(((wm + mt * 16 + a_r) * SKA2 + ks + a_s * 8) * 2);
                LDMATRIX_X4(af[mt][0], af[mt][1], af[mt][2], af[mt][3], addr);
            }
            #pragma unroll
            for (int np = 0; np < 2; np++) {
                uint32_t addr = bB + (uint32_t)(((ks + (b_s & 1) * 8 + b_k) * SKB2 + wn + np * 16 + (b_s >> 1) * 8) * 2);
                uint32_t r0, r1, r2, r3;
                LDMATRIX_X4_T(r0, r1, r2, r3, addr);
                bf[2*np][0] = r0; bf[2*np][1] = r1;
                bf[2*np+1][0] = r2; bf[2*np+1][1] = r3;
            }
            #pragma unroll
            for (int mt = 0; mt < 4; mt++)
                #pragma unroll
                for (int nt = 0; nt < 4; nt++)
                    HMMA16816(acc[mt][nt], af[mt][0], af[mt][1], af[mt][2], af[mt][3], bf[nt][0], bf[nt][1]);
        }
    };

    const int nIter = K / 32;
    issueT(0, 0);
    issueT(32, 1);
    int stg = 0;
    for (int it = 0; it < nIter; it++) {
        if (it < nIter - 1) {
            asm volatile("cp.async.wait_group 1;");
        } else {
            asm volatile("cp.async.wait_group 0;");
        }
        __syncthreads();
        compute(stg);
        if (it + 2 < nIter) {
            int ns = stg + 2; if (ns >= 3) ns -= 3;
            issueT((it + 2) * 32, ns);
        }
        if (++stg == 3) stg = 0;
    }

    if (SPLIT) {
        float* Cz = (float*)Cv + (long long)(bz + zoff) * M * Nn;
        #pragma unroll
        for (int mt = 0; mt < 4; mt++) {
            int r0 = by * 128 + wm + mt * 16 + lr;
            int r1 = r0 + 8;
            #pragma unroll
            for (int nt = 0; nt < 4; nt++) {
                int col = bx * 128 + wn + nt * 8 + 2 * lc;
                if (r0 < M) *(float2*)&Cz[(long long)r0 * Nn + col] = make_float2(acc[mt][nt][0], acc[mt][nt][1]);
                if (r1 < M) *(float2*)&Cz[(long long)r1 * Nn + col] = make_float2(acc[mt][nt][2], acc[mt][nt][3]);
            }
        }
        return;
    }

    const float bninv = rsqrtf(1.0f + 1e-5f);
    const long long SZr = (long long)NGRAPH * 3328;
    #pragma unroll
    for (int mt = 0; mt < 4; mt++) {
        int r0 = by * 128 + wm + mt * 16 + lr;
        int r1 = r0 + 8;
        #pragma unroll
        for (int nt = 0; nt < 4; nt++) {
            int col = bx * 128 + wn + nt * 8 + 2 * lc;
            float b0 = __ldg(bias + col);
            float b1 = __ldg(bias + col + 1);
            float g0 = 1.f, g1 = 1.f, be0 = 0.f, be1 = 0.f;
            if (EPI >= 2) {
                g0 = __ldg(bng + col) * bninv;  g1 = __ldg(bng + col + 1) * bninv;
                be0 = __ldg(bnb + col);         be1 = __ldg(bnb + col + 1);
            }
            float v00 = acc[mt][nt][0], v01 = acc[mt][nt][1];
            float v10 = acc[mt][nt][2], v11 = acc[mt][nt][3];
            if (EPI == 3) {
                float2 s0 = make_float2(0.f, 0.f), s1 = make_float2(0.f, 0.f);
                #pragma unroll
                for (int z = 0; z < 4; z++) {
                    float2 t0 = *(const float2*)&red[z * SZr + (long long)r0 * Nn + col];
                    float2 t1 = *(const float2*)&red[z * SZr + (long long)r1 * Nn + col];
                    s0.x += t0.x; s0.y += t0.y;
                    s1.x += t1.x; s1.y += t1.y;
                }
                v00 += s0.x; v01 += s0.y;
                v10 += s1.x; v11 += s1.y;
            }
            v00 += b0; v01 += b1; v10 += b0; v11 += b1;
            if (EPI >= 2) {
                v00 = v00 * g0 + be0; v01 = v01 * g1 + be1;
                v10 = v10 * g0 + be0; v11 = v11 * g1 + be1;
            }
            if (EPI >= 1) {
                v00 = fmaxf(v00, 0.f); v01 = fmaxf(v01, 0.f);
                v10 = fmaxf(v10, 0.f); v11 = fmaxf(v11, 0.f);
            }
            if (CH) {
                __half* Ch = (__half*)Cv;
                if (r0 < M) *(__half2*)&Ch[(long long)r0 * Nn + col] = __floats2half2_rn(v00, v01);
                if (r1 < M) *(__half2*)&Ch[(long long)r1 * Nn + col] = __floats2half2_rn(v10, v11);
            } else {
                float* Cf = (float*)Cv;
                if (r0 < M) *(float2*)&Cf[(long long)r0 * Nn + col] = make_float2(v00, v01);
                if (r1 < M) *(float2*)&Cf[(long long)r1 * Nn + col] = make_float2(v10, v11);
            }
        }
    }
}

// ---------------------------------------------------------------------------
// FUSED gather + conv MLP: C = relu(bn(relu((feat_i + sum_j feat_j) @ W1 + b1) @ W2 + b2))
// K1 = input dim (64 or 128); mid = out = 128. Gather writes Atile in smem.
// ---------------------------------------------------------------------------
template<int K1>
__global__ __launch_bounds__(256, 2) void gconv_fused_kernel(
    int M,
    const uint4* __restrict__ feat,
    const int* __restrict__ rowptr, const int* __restrict__ srclist,
    const __half* __restrict__ W1, const float* __restrict__ b1,
    const __half* __restrict__ W2, const float* __restrict__ b2,
    const float* __restrict__ bng, const float* __restrict__ bnb,
    __half* __restrict__ C)
{
    extern __shared__ __half dsm[];
    __half* Atile  = dsm;                       // 128 x SKB2
    __half* H1     = dsm + AT_STG;              // 128 x SKB2
    __half* BsBase = dsm + 2 * AT_STG;          // 3 stages

    constexpr int LROW = K1 / 8;    // uint4 per feature row
    constexpr int LV = LROW / 4;    // uint4 per thread (4 threads/row)

    const int tid = threadIdx.x, by = blockIdx.y;
    const int warp = tid >> 5, lane = tid & 31;
    const int wm = (warp >> 2) * 64;
    const int wn = (warp & 3) * 32;
    const int lr = lane >> 2;
    const int lc = lane & 3;
    const int a_r = lane & 15, a_s = lane >> 4;
    const int b_k = lane & 7,  b_s = lane >> 3;

    // ---- phase 0: gather rows into Atile (2 passes, 64 rows each, 4 thr/row) ----
    #pragma unroll
    for (int p = 0; p < 2; p++) {
        const int row = p * 64 + (tid >> 2);
        const int gr = by * 128 + row;
        const int qb = (tid & 3) * LV;
        float2 a[LV][4];
        if (gr < M) {
            #pragma unroll
            for (int l = 0; l < LV; l++) {
                uint4 v = __ldg(&feat[(long long)gr * LROW + qb + l]);
                a[l][0] = h2f2(v.x); a[l][1] = h2f2(v.y);
                a[l][2] = h2f2(v.z); a[l][3] = h2f2(v.w);
            }
            int j = __ldg(rowptr + gr);
            const int end = __ldg(rowptr + gr + 1);
            for (; j + 1 < end; j += 2) {
                int s0 = __ldg(srclist + j);
                int s1 = __ldg(srclist + j + 1);
                #pragma unroll
                for (int l = 0; l < LV; l++) {
                    uint4 t0 = __ldg(&feat[(long long)s0 * LROW + qb + l]);
                    uint4 t1 = __ldg(&feat[(long long)s1 * LROW + qb + l]);
                    acc4(a[l], t0); acc4(a[l], t1);
                }
            }
            if (j < end) {
                int s0 = __ldg(srclist + j);
                #pragma unroll
                for (int l = 0; l < LV; l++) {
                    uint4 t0 = __ldg(&feat[(long long)s0 * LROW + qb + l]);
                    acc4(a[l], t0);
                }
            }
        } else {
            #pragma unroll
            for (int l = 0; l < LV; l++)
                #pragma unroll
                for (int q = 0; q < 4; q++) a[l][q] = make_float2(0.f, 0.f);
        }
        #pragma unroll
        for (int l = 0; l < LV; l++) {
            __half2 h0 = __floats2half2_rn(a[l][0].x, a[l][0].y);
            __half2 h1 = __floats2half2_rn(a[l][1].x, a[l][1].y);
            __half2 h2 = __floats2half2_rn(a[l][2].x, a[l][2].y);
            __half2 h3 = __floats2half2_rn(a[l][3].x, a[l][3].y);
            uint4 o;
            o.x = *(uint32_t*)&h0; o.y = *(uint32_t*)&h1;
            o.z = *(uint32_t*)&h2; o.w = *(uint32_t*)&h3;
            *(uint4*)&Atile[row * SKB2 + (qb + l) * 8] = o;
        }
    }
    __syncthreads();

    float acc[4][4][4];
    #pragma unroll
    for (int i = 0; i < 4; i++)
        #pragma unroll
        for (int j = 0; j < 4; j++)
            #pragma unroll
            for (int t = 0; t < 4; t++) acc[i][j][t] = 0.0f;

    auto issueB = [&](const __half* B, int kk, int stg) {
        __half* Bs = BsBase + stg * B_STG;
        #pragma unroll
        for (int q = 0; q < 2; q++) {
            int c = tid + q * 256;
            int row = c >> 4, nc = (c & 15) * 8;
            uint32_t sb = smem_u32(&Bs[row * SKB2 + nc]);
            cp16(sb, B + (long long)(kk + row) * 128 + nc, 16);
        }
    };
    auto computeAB = [&](uint32_t aB, uint32_t bB) {
        #pragma unroll
        for (int ks = 0; ks < 32; ks += 16) {
            uint32_t af[4][4], bf[4][2];
            #pragma unroll
            for (int mt = 0; mt < 4; mt++) {
                uint32_t addr = aB + (uint32_t)(((wm + mt * 16 + a_r) * SKB2 + ks + a_s * 8) * 2);
                LDMATRIX_X4(af[mt][0], af[mt][1], af[mt][2], af[mt][3], addr);
            }
            #pragma unroll
            for (int np = 0; np < 2; np++) {
                uint32_t addr = bB + (uint32_t)(((ks + (b_s & 1) * 8 + b_k) * SKB2 + wn + np * 16 + (b_s >> 1) * 8) * 2);
                uint32_t r0, r1, r2, r3;
                LDMATRIX_X4_T(r0, r1, r2, r3, addr);
                bf[2*np][0] = r0; bf[2*np][1] = r1;
                bf[2*np+1][0] = r2; bf[2*np+1][1] = r3;
            }
            #pragma unroll
            for (int mt = 0; mt < 4; mt++)
                #pragma unroll
                for (int nt = 0; nt < 4; nt++)
                    HMMA16816(acc[mt][nt], af[mt][0], af[mt][1], af[mt][2], af[mt][3], bf[nt][0], bf[nt][1]);
        }
    };
    auto bpipe = [&](const __half* W, uint32_t aBase, int nIter) {
        issueB(W, 0, 0); CP_COMMIT();
        issueB(W, 32, 1); CP_COMMIT();
        int stg = 0;
        for (int it = 0; it < nIter; it++) {
            if (it < nIter - 1) asm volatile("cp.async.wait_group 1;");
            else                asm volatile("cp.async.wait_group 0;");
            __syncthreads();
            computeAB(aBase + (uint32_t)(it * 64), smem_u32(BsBase + stg * B_STG));
            if (it + 2 < nIter) {
                int ns = stg + 2; if (ns >= 3) ns -= 3;
                issueB(W, (it + 2) * 32, ns); CP_COMMIT();
            }
            if (++stg == 3) stg = 0;
        }
    };

    // ---- phase 1: acc = Atile @ W1 ----
    bpipe(W1, smem_u32(Atile), K1 / 32);
    __syncthreads();

    // ---- epilogue 1: H1 = relu(acc + b1) ----
    #pragma unroll
    for (int mt = 0; mt < 4; mt++) {
        int r0 = wm + mt * 16 + lr;
        int r1 = r0 + 8;
        #pragma unroll
        for (int nt = 0; nt < 4; nt++) {
            int col = wn + nt * 8 + 2 * lc;
            float bb0 = __ldg(b1 + col);
            float bb1 = __ldg(b1 + col + 1);
            float v00 = fmaxf(acc[mt][nt][0] + bb0, 0.f);
            float v01 = fmaxf(acc[mt][nt][1] + bb1, 0.f);
            float v10 = fmaxf(acc[mt][nt][2] + bb0, 0.f);
            float v11 = fmaxf(acc[mt][nt][3] + bb1, 0.f);
            *(__half2*)&H1[r0 * SKB2 + col] = __floats2half2_rn(v00, v01);
            *(__half2*)&H1[r1 * SKB2 + col] = __floats2half2_rn(v10, v11);
            acc[mt][nt][0] = 0.f; acc[mt][nt][1] = 0.f;
            acc[mt][nt][2] = 0.f; acc[mt][nt][3] = 0.f;
        }
    }
    __syncthreads();

    // ---- phase 2: acc = H1 @ W2 (K = 128) ----
    bpipe(W2, smem_u32(H1), 4);

    // ---- epilogue 2: C = relu(bn(acc + b2)) ----
    const float bninv = rsqrtf(1.0f + 1e-5f);
    #pragma unroll
    for (int mt = 0; mt < 4; mt++) {
        int r0 = by * 128 + wm + mt * 16 + lr;
        int r1 = r0 + 8;
        #pragma unroll
        for (int nt = 0; nt < 4; nt++) {
            int col = wn + nt * 8 + 2 * lc;
            float bb0 = __ldg(b2 + col), bb1 = __ldg(b2 + col + 1);
            float g0 = __ldg(bng + col) * bninv, g1 = __ldg(bng + col + 1) * bninv;
            float be0 = __ldg(bnb + col), be1 = __ldg(bnb + col + 1);
            float v00 = fmaxf((acc[mt][nt][0] + bb0) * g0 + be0, 0.f);
            float v01 = fmaxf((acc[mt][nt][1] + bb1) * g1 + be1, 0.f);
            float v10 = fmaxf((acc[mt][nt][2] + bb0) * g0 + be0, 0.f);
            float v11 = fmaxf((acc[mt][nt][3] + bb1) * g1 + be1, 0.f);
            if (r0 < M) *(__half2*)&C[(long long)r0 * 128 + col] = __floats2half2_rn(v00, v01);
            if (r1 < M) *(__half2*)&C[(long long)r1 * 128 + col] = __floats2half2_rn(v10, v11);
        }
    }
}

// ---------------------------------------------------------------------------
extern "C" void kernel_launch(void* const* d_in, const int* in_sizes, int n_in,
                              void* d_out, int out_size) {
    const float* x     = (const float*)d_in[0];
    const int*   ei    = (const int*)  d_in[1];
    const int*   src   = ei;
    const int*   dst   = ei + NEDGES;
    const int*   batch = (const int*)  d_in[2];
    const float* fp    = (const float*)d_in[3];
    const float* c1w1 = (const float*)d_in[4],  *c1b1 = (const float*)d_in[5];
    const float* c1w2 = (const float*)d_in[6],  *c1b2 = (const float*)d_in[7];
    const float* c2w1 = (const float*)d_in[8],  *c2b1 = (const float*)d_in[9];
    const float* c2w2 = (const float*)d_in[10], *c2b2 = (const float*)d_in[11];
    const float* c3w1 = (const float*)d_in[12], *c3b1 = (const float*)d_in[13];
    const float* c3w2 = (const float*)d_in[14], *c3b2 = (const float*)d_in[15];
    const float* bn1g = (const float*)d_in[16], *bn1b = (const float*)d_in[17];
    const float* bn2g = (const float*)d_in[18], *bn2b = (const float*)d_in[19];
    const float* bn3g = (const float*)d_in[20], *bn3b = (const float*)d_in[21];
    const float* o1w  = (const float*)d_in[22], *o1b  = (const float*)d_in[23];
    const float* obng = (const float*)d_in[24], *obnb = (const float*)d_in[25];
    const float* o3w  = (const float*)d_in[26], *o3b  = (const float*)d_in[27];
    float* out = (float*)d_out;

    __half *xh, *aggrh, *tmph, *hh, *wh, *poolh;
    float *scr;
    int *deg, *cursor, *rowptr, *srclist, *gstart, *bsum;
    cudaGetSymbolAddress((void**)&xh,      g_xh);
    cudaGetSymbolAddress((void**)&aggrh,   g_aggrh);
    cudaGetSymbolAddress((void**)&tmph,    g_tmph);
    cudaGetSymbolAddress((void**)&hh,      g_hh);
    cudaGetSymbolAddress((void**)&wh,      g_wh);
    cudaGetSymbolAddress((void**)&poolh,   g_poolh);
    cudaGetSymbolAddress((void**)&scr,     g_scr);
    cudaGetSymbolAddress((void**)&deg,     g_deg);
    cudaGetSymbolAddress((void**)&cursor,  g_cursor);
    cudaGetSymbolAddress((void**)&rowptr,  g_rowptr);
    cudaGetSymbolAddress((void**)&srclist, g_srclist);
    cudaGetSymbolAddress((void**)&gstart,  g_gstart);
    cudaGetSymbolAddress((void**)&bsum,    g_bsum);

    cudaFuncSetAttribute(hgemm16_kernel<1,0,true>,  cudaFuncAttributeMaxDynamicSharedMemorySize, HG_SMEM);
    cudaFuncSetAttribute(hgemm16_kernel<2,0,true>,  cudaFuncAttributeMaxDynamicSharedMemorySize, HG_SMEM);
    cudaFuncSetAttribute(hgemm16_kernel<0,1,false>, cudaFuncAttributeMaxDynamicSharedMemorySize, HG_SMEM);
    cudaFuncSetAttribute(hgemm16_kernel<3,0,true>,  cudaFuncAttributeMaxDynamicSharedMemorySize, HG_SMEM);
    cudaFuncSetAttribute(gconv_fused_kernel<64>,  cudaFuncAttributeMaxDynamicSharedMemorySize, GF_SMEM);
    cudaFuncSetAttribute(gconv_fused_kernel<128>, cudaFuncAttributeMaxDynamicSharedMemorySize, GF_SMEM);

    const int T = 256;
    const int gy = (NNODES + 127) / 128;
    const long long SZ = (long long)NGRAPH * 3328;

    // ---- fork/join infrastructure ----
    cudaStream_t sB, sC, sP;
    cudaStreamCreateWithFlags(&sB, cudaStreamNonBlocking);
    cudaStreamCreateWithFlags(&sC, cudaStreamNonBlocking);
    cudaStreamCreateWithFlags(&sP, cudaStreamNonBlocking);
    cudaEvent_t evRoot, evB, evC, evH[3], evP[3];
    cudaEventCreateWithFlags(&evRoot, cudaEventDisableTiming);
    cudaEventCreateWithFlags(&evB,    cudaEventDisableTiming);
    cudaEventCreateWithFlags(&evC,    cudaEventDisableTiming);
    for (int i = 0; i < 3; i++) {
        cudaEventCreateWithFlags(&evH[i], cudaEventDisableTiming);
        cudaEventCreateWithFlags(&evP[i], cudaEventDisableTiming);
    }

    cudaEventRecord(evRoot, 0);
    cudaStreamWaitEvent(sB, evRoot, 0);
    cudaStreamWaitEvent(sC, evRoot, 0);

    // ---- sC: x convert + fingerprint + conv weights ----
    {
        f2h_kernel<<<(NNODES * 32 + T - 1) / T, T, 0, sC>>>((const float2*)x, (__half2*)xh, NNODES * 32);
        fp_copy_kernel<<<dim3((1536 + T - 1) / T, NGRAPH), T, 0, sC>>>((const float4*)fp, (uint2*)poolh);
        WConvArgs wc = {};
        wc.seg[0] = { (const float2*)c1w1, (__half2*)(wh + W_C1W1), 4096 };
        wc.seg[1] = { (const float2*)c1w2, (__half2*)(wh + W_C1W2), 8192 };
        wc.seg[2] = { (const float2*)c2w1, (__half2*)(wh + W_C2W1), 8192 };
        wc.seg[3] = { (const float2*)c2w2, (__half2*)(wh + W_C2W2), 8192 };
        wc.seg[4] = { (const float2*)c3w1, (__half2*)(wh + W_C3W1), 16384 };
        wc.seg[5] = { (const float2*)c3w2, (__half2*)(wh + W_C3W2), 32768 };
        wc.total = 4096 + 8192 + 8192 + 8192 + 16384 + 32768;
        wconv_kernel<<<256, T, 0, sC>>>(wc);
        cudaEventRecord(evC, sC);
    }
    // ---- sB: big weight converts, then fingerprint-part of readout GEMM1 ----
    {
        WConvArgs wb = {};
        wb.seg[0] = { (const float2*)o3w, (__half2*)(wh + W_O3W), 212992 };
        wb.seg[1] = { (const float2*)o1w, (__half2*)(wh + W_O1W), 11075584 };
        wb.total = 212992 + 11075584;
        wconv_kernel<<<2048, T, 0, sB>>>(wb);
        cudaStreamWaitEvent(sB, evC, 0);
        hgemm16_kernel<0,1,false><<<dim3(3328 / 128, 4, 4), T, HG_SMEM, sB>>>(
            NGRAPH, 3328, 1536, RDIM, 0, poolh + 512, wh + W_O1W + (long long)512 * 3328,
            nullptr, nullptr, nullptr, nullptr, scr);
        cudaEventRecord(evB, sB);
    }
    // ---- main: CSR build (multi-block scan) ----
    cudaMemsetAsync(deg, 0, NNODES * sizeof(int), 0);
    hist_kernel<<<(NEDGES / 4 + T - 1) / T, T>>>(dst, deg);
    bsum_kernel<<<NSCANB, 1024>>>(deg, bsum);
    boff_kernel<<<1, 1>>>(bsum, rowptr);
    rowptr_kernel<<<NSCANB, 1024>>>(deg, bsum, rowptr, cursor);
    fill_kernel<<<(NEDGES / 4 + T - 1) / T, T>>>(src, dst, cursor, srclist);
    gstart_kernel<<<3, 256>>>(batch, gstart);
    cudaStreamWaitEvent(0, evC, 0);

    // ---- conv1: fused gather+MLP  xh -> hh ----
    gconv_fused_kernel<64><<<dim3(1, gy), T, GF_SMEM>>>(NNODES, (const uint4*)xh, rowptr, srclist,
        wh + W_C1W1, c1b1, wh + W_C1W2, c1b2, bn1g, bn1b, hh);
    cudaEventRecord(evH[0], 0);
    cudaStreamWaitEvent(sP, evH[0], 0);
    seg_pool_h_kernel<<<NGRAPH, 64, 0, sP>>>((const __half2*)hh, gstart, (__half2*)poolh, 64, 0);
    cudaEventRecord(evP[0], sP);

    // ---- conv2: fused gather+MLP  hh -> tmph (no pool wait needed: writes a fresh buffer) ----
    gconv_fused_kernel<128><<<dim3(1, gy), T, GF_SMEM>>>(NNODES, (const uint4*)hh, rowptr, srclist,
        wh + W_C2W1, c2b1, wh + W_C2W2, c2b2, bn2g, bn2b, tmph);
    cudaEventRecord(evH[1], 0);
    cudaStreamWaitEvent(sP, evH[1], 0);
    seg_pool_h_kernel<<<NGRAPH, 64, 0, sP>>>((const __half2*)tmph, gstart, (__half2*)poolh, 64, 64);
    cudaEventRecord(evP[1], sP);

    // ---- conv3 (unfused): gather tmph -> aggrh; GEMM1 aggrh -> hh; GEMM2 hh -> aggrh ----
    gather_aggr_h_kernel<128><<<(NNODES * 16 + T - 1) / T, T>>>((const uint4*)tmph, rowptr, srclist, (uint4*)aggrh);
    cudaStreamWaitEvent(0, evP[0], 0);   // pool1 reads hh; must finish before hh overwrite
    hgemm16_kernel<1,0,true><<<dim3(2, gy), T, HG_SMEM>>>(NNODES, 256, 128, 128, 0, aggrh, wh + W_C3W1, c3b1, nullptr, nullptr, nullptr, hh);
    hgemm16_kernel<2,0,true><<<dim3(2, gy), T, HG_SMEM>>>(NNODES, 256, 256, 256, 0, hh, wh + W_C3W2, c3b2, bn3g, bn3b, nullptr, aggrh);
    cudaEventRecord(evH[2], 0);
    cudaStreamWaitEvent(sP, evH[2], 0);
    seg_pool_h_kernel<<<NGRAPH, 128, 0, sP>>>((const __half2*)aggrh, gstart, (__half2*)poolh, 128, 128);
    cudaEventRecord(evP[2], sP);

    // ---- GEMM1 part-A (K=512) with fused 4-slot reduce + bias/bn/relu -> tmph fp16 ----
    cudaStreamWaitEvent(0, evP[2], 0);
    cudaStreamWaitEvent(0, evB, 0);
    hgemm16_kernel<3,0,true><<<dim3(3328 / 128, 4, 1), T, HG_SMEM>>>(
        NGRAPH, 3328, 512, RDIM, 0, poolh, wh + W_O1W, o1b, obng, obnb, scr, tmph);

    // ---- readout GEMM2: split-K=8 ----
    float* scr2 = scr + 5 * SZ;
    hgemm16_kernel<0,1,false><<<dim3(1, 4, 8), T, HG_SMEM>>>(NGRAPH, 128, 416, 3328, 0, tmph, wh + W_O3W, nullptr, nullptr, nullptr, nullptr, scr2);
    final_reduce_kernel<<<(NGRAPH * 128 + T - 1) / T, T>>>(scr2, o3b, out);

    // ---- cleanup ----
    cudaEventDestroy(evRoot); cudaEventDestroy(evB); cudaEventDestroy(evC);
    for (int i = 0; i < 3; i++) { cudaEventDestroy(evH[i]); cudaEventDestroy(evP[i]); }
    cudaStreamDestroy(sB); cudaStreamDestroy(sC); cudaStreamDestroy(sP);
}